// round 2
// baseline (speedup 1.0000x reference)
#include <cuda_runtime.h>

// cumulative mean over dim 0 of x[8192, 4096] fp32.
// out[r, c] = (sum_{i<=r} x[i, c]) / (r + 1)
//
// Single-pass column-wise prefix sum with decoupled lookback.
//   - virtualized block ids (global ticket) -> lookback is deadlock-free
//     under ANY block scheduling order.
//   - block = 512 threads = 64 float4-column-quads x 8 row-groups
//   - each thread holds 16 rows (float4) in registers -> chunk = 128 rows x 256 cols
//   - streaming loads/stores; one read + one write of the 256MB.

#define ROWS 8192
#define COLS 4096
#define CHUNK_ROWS 128
#define NCHUNKS (ROWS / CHUNK_ROWS)   // 64
#define QPB 64                        // float4 column-quads per block (256 cols)
#define YG 8                          // row groups per block
#define NTHREADS (QPB * YG)           // 512
#define RPT 16                        // rows per thread (register resident)
#define NCB (COLS / (QPB * 4))        // 16 column blocks
#define GQ (NCB * QPB)                // 1024 global quads per chunk
#define NBLOCKS (NCB * NCHUNKS)       // 1024

// Scratch (no allocation allowed): partials + lookback flags + ticket.
__device__ float4 g_agg[NCHUNKS][GQ];    // 1 MB
__device__ float4 g_incl[NCHUNKS][GQ];   // 1 MB
__device__ int    g_flag[NCB][NCHUNKS];  // 4 KB  (0 = empty, 1 = agg ready, 2 = inclusive ready)
__device__ unsigned int g_ticket;

__device__ __forceinline__ int ld_acq(const int* p) {
    int v;
    asm volatile("ld.acquire.gpu.global.b32 %0, [%1];" : "=r"(v) : "l"(p) : "memory");
    return v;
}
__device__ __forceinline__ void st_rel(int* p, int v) {
    asm volatile("st.release.gpu.global.b32 [%0], %1;" :: "l"(p), "r"(v) : "memory");
}
__device__ __forceinline__ float4 f4add(float4 a, float4 b) {
    a.x += b.x; a.y += b.y; a.z += b.z; a.w += b.w; return a;
}

__global__ void init_flags_kernel() {
    int i = threadIdx.x;
    if (i < NCB * NCHUNKS) ((int*)g_flag)[i] = 0;
    if (i == 0) g_ticket = 0u;
}

__global__ __launch_bounds__(NTHREADS)
void cummean_kernel(const float* __restrict__ x, float* __restrict__ out) {
    // ---- Virtualized block id: chunk-major ticket, deadlock-free lookback ----
    __shared__ unsigned int sh_vbid;
    if (threadIdx.x == 0) sh_vbid = atomicAdd(&g_ticket, 1u);
    __syncthreads();
    const unsigned int vbid = sh_vbid;
    const int cb    = vbid & (NCB - 1);      // 0..15 column block
    const int chunk = vbid >> 4;             // 0..63 row chunk (strictly ordered)

    const int tid   = threadIdx.x;
    const int quad  = tid & (QPB - 1);       // which float4 column quad
    const int yg    = tid >> 6;              // row group 0..7
    const int col   = cb * (QPB * 4) + quad * 4;
    const int row0  = chunk * CHUNK_ROWS + yg * RPT;

    // ---- Phase 1: load 16 rows (streaming), in-register prefix ----
    const float4* xp = reinterpret_cast<const float4*>(x + (size_t)row0 * COLS) + (col >> 2);
    float4 v[RPT];
#pragma unroll
    for (int i = 0; i < RPT; i++) v[i] = __ldcs(xp + i * (COLS / 4));
#pragma unroll
    for (int i = 1; i < RPT; i++) v[i] = f4add(v[i], v[i - 1]);

    // ---- Phase 2: block scan across the 8 row-groups through SMEM ----
    __shared__ float4 sh_gs[YG][QPB];
    __shared__ float4 sh_off[QPB];
    sh_gs[yg][quad] = v[RPT - 1];
    __syncthreads();

    float4 excl = make_float4(0.f, 0.f, 0.f, 0.f);  // exclusive sum of groups below mine
    float4 aggB = make_float4(0.f, 0.f, 0.f, 0.f);  // whole-block aggregate for my quad
#pragma unroll
    for (int y = 0; y < YG; y++) {
        float4 g = sh_gs[y][quad];
        if (y < yg) excl = f4add(excl, g);
        aggB = f4add(aggB, g);
    }

    const int gq = cb * QPB + quad;
    int* flagp = &g_flag[cb][chunk];

    // Publish block aggregate (flag = 1)
    if (chunk > 0 && yg == 0) {
        __stcg(&g_agg[chunk][gq], aggB);
        __threadfence();
    }
    __syncthreads();
    if (chunk > 0 && tid == 0) st_rel(flagp, 1);

    // ---- Phase 3: decoupled lookback (yg==0 warps only: tids 0..63) ----
    if (yg == 0) {
        float4 off = make_float4(0.f, 0.f, 0.f, 0.f);
        if (chunk > 0) {
            const int lane = tid & 31;
            int p = chunk - 1;
            for (;;) {
                int f = 0;
                if (lane == 0) { while ((f = ld_acq(&g_flag[cb][p])) == 0) {} }
                f = __shfl_sync(0xffffffffu, f, 0);
                if (f == 2) { off = f4add(off, __ldcg(&g_incl[p][gq])); break; }
                off = f4add(off, __ldcg(&g_agg[p][gq]));
                --p;
            }
        }
        __stcg(&g_incl[chunk][gq], f4add(off, aggB));
        __threadfence();
        sh_off[quad] = off;
    }
    __syncthreads();
    if (tid == 0) st_rel(flagp, 2);  // inclusive ready

    // ---- Phase 4: add offsets, scale by 1/(row+1), streaming store ----
    float4 base = f4add(sh_off[quad], excl);
    float4* op = reinterpret_cast<float4*>(out + (size_t)row0 * COLS) + (col >> 2);
#pragma unroll
    for (int i = 0; i < RPT; i++) {
        float r = 1.0f / (float)(row0 + i + 1);
        float4 w;
        w.x = (v[i].x + base.x) * r;
        w.y = (v[i].y + base.y) * r;
        w.z = (v[i].z + base.z) * r;
        w.w = (v[i].w + base.w) * r;
        __stcs(op + i * (COLS / 4), w);
    }
}

extern "C" void kernel_launch(void* const* d_in, const int* in_sizes, int n_in,
                              void* d_out, int out_size) {
    const float* x = (const float*)d_in[0];
    float* out = (float*)d_out;
    // Reset lookback flags + ticket every launch (graph-replay safe), then scan.
    init_flags_kernel<<<1, 1024>>>();
    cummean_kernel<<<NBLOCKS, NTHREADS>>>(x, out);
}